// round 4
// baseline (speedup 1.0000x reference)
#include <cuda_runtime.h>
#include <cuda_fp16.h>
#include <stdint.h>

#define ED 128
#define DHALF 64
#define TILE_M 128
#define THREADS 256
#define SB 136          // fp16 row stride (272B) -> conflict-free ldmatrix
#define ROWB 272        // SB*2 bytes

// ---------------- device globals ----------------
__device__ __half g_W1h[ED * ED];
__device__ int g_idx64;

// ---------------- helpers ----------------
__device__ __forceinline__ uint32_t smem_u32(const void* p) {
    uint32_t a;
    asm("{ .reg .u64 t; cvta.to.shared.u64 t, %1; cvt.u32.u64 %0, t; }" : "=r"(a) : "l"(p));
    return a;
}
__device__ __forceinline__ void ldsm_x4(uint32_t* r, uint32_t addr) {
    asm volatile("ldmatrix.sync.aligned.m8n8.x4.shared.b16 {%0,%1,%2,%3}, [%4];"
                 : "=r"(r[0]), "=r"(r[1]), "=r"(r[2]), "=r"(r[3]) : "r"(addr));
}
__device__ __forceinline__ void mma16816(float* c, const uint32_t* a, uint32_t b0, uint32_t b1) {
    asm volatile("mma.sync.aligned.m16n8k16.row.col.f32.f16.f16.f32 "
                 "{%0,%1,%2,%3}, {%4,%5,%6,%7}, {%8,%9}, {%0,%1,%2,%3};"
                 : "+f"(c[0]), "+f"(c[1]), "+f"(c[2]), "+f"(c[3])
                 : "r"(a[0]), "r"(a[1]), "r"(a[2]), "r"(a[3]), "r"(b0), "r"(b1));
}
__device__ __forceinline__ void cp16(uint32_t dst, const void* src) {
    asm volatile("cp.async.cg.shared.global [%0], [%1], 16;" :: "r"(dst), "l"(src) : "memory");
}
__device__ __forceinline__ void cp_commit() {
    asm volatile("cp.async.commit_group;" ::: "memory");
}
__device__ __forceinline__ void cp_wait0() {
    asm volatile("cp.async.wait_group 0;" ::: "memory");
}

// smem layout (bytes)
#define SM_PART 0                       // float[4][128]
#define SM_B1   2048                    // float[128]
#define SM_W2   2560                    // float[128]
#define SM_AH   3072                    // 128 x SB fp16
#define SM_AL   (SM_AH + TILE_M * ROWB) // 128 x SB fp16
#define SM_ST0  (SM_AL + TILE_M * ROWB) // 128 x 512B fp32 staging (512-aligned)
#define SM_ST1  (SM_ST0 + 65536)
#define SMEM_BYTES (SM_ST1 + 65536)

// ---------------- prep ----------------
__global__ void pip_prep(const float* __restrict__ W1, const void* __restrict__ idxl,
                         long long P, long long Nnodes) {
    int i = blockIdx.x * blockDim.x + threadIdx.x;
    if (i < ED * ED) g_W1h[i] = __float2half_rn(W1[i]);
    if (blockIdx.x == 0 && threadIdx.x == 0) {
        const unsigned long long* p64 = (const unsigned long long*)idxl;
        long long n = 512;
        if (2 * n > P) n = P / 2;
        int ok = 1;
        for (long long k = 0; k < n; k++)
            if (p64[k] >= (unsigned long long)Nnodes) { ok = 0; break; }
        g_idx64 = ok;
    }
}

// ---------------- main persistent kernel ----------------
extern "C" __global__ void __launch_bounds__(THREADS, 1)
pip_main(const float* __restrict__ g1, const float* __restrict__ g2,
         const void* __restrict__ idxl, const void* __restrict__ idxr,
         const float* __restrict__ b1, const float* __restrict__ W2,
         const float* __restrict__ b2, float* __restrict__ out,
         long long P, long long Nnodes) {
    extern __shared__ char smem[];
    const uint32_t sb = smem_u32(smem);
    const int tid = threadIdx.x;
    const int wid = tid >> 5;
    const int lid = tid & 31;
    const int is64 = g_idx64;

    // ---- stage b1 / W2 ----
    for (int i = tid; i < ED; i += THREADS) {
        ((float*)(smem + SM_B1))[i] = b1[i];
        ((float*)(smem + SM_W2))[i] = W2[i];
    }

    // ---- stage W1h into ST0 temporarily, ldmatrix B frags into registers ----
    for (int i = tid; i < ED * 32; i += THREADS) {   // uint2 = 4 halfs
        int n = i >> 5, kq = i & 31;
        *(uint2*)(smem + SM_ST0 + n * ROWB + kq * 8) = ((const uint2*)g_W1h)[i];
    }
    __syncthreads();

    const int wm = wid >> 2;        // 0..1 -> m0 = wm*64
    const int wn = wid & 3;         // 0..3 -> n0 = wn*32
    const int m0 = wm * 64;
    const int n0 = wn * 32;
    const int a_row = (lid & 7) + ((lid >> 3) & 1) * 8;
    const int a_kad = ((lid >> 4) & 1) * 8;
    const int b_row = (lid & 7) + ((lid >> 4) & 1) * 8;
    const int b_kad = ((lid >> 3) & 1) * 8;

    uint32_t breg[8][8];
#pragma unroll
    for (int ks = 0; ks < 8; ks++) {
        uint32_t bo0 = (uint32_t)((n0 + b_row) * ROWB) + (uint32_t)(ks * 16 + b_kad) * 2;
        uint32_t bo1 = (uint32_t)((n0 + 16 + b_row) * ROWB) + (uint32_t)(ks * 16 + b_kad) * 2;
        ldsm_x4(&breg[ks][0], sb + SM_ST0 + bo0);
        ldsm_x4(&breg[ks][4], sb + SM_ST0 + bo1);
    }
    __syncthreads();   // done reading ST0; gather may now overwrite it

    const float b2v = b2[0];
    const long long nTiles = (P + TILE_M - 1) / TILE_M;
    const long long grid = gridDim.x;

    // gather role: thread -> (row = tid>>1, half = tid&1)
    const int grow = tid >> 1;
    const int ghalf = tid & 1;
    const void* g_isrc = ghalf ? idxr : idxl;
    const float* g_src = ghalf ? g2 : g1;
    const uint32_t g_dbase = (uint32_t)(grow * 512) +
                             (((uint32_t)(ghalf * 256)) ^ (((uint32_t)grow & 7) << 4) &
                              0);  // placeholder (computed per-i below)
    (void)g_dbase;

    // convert role: thread -> (row = tid&127, half = tid>>7)
    const int crow = tid & 127;
    const int chalf = tid >> 7;

    long long t = blockIdx.x;
    int par = 0;

    // ---- prologue: gather tile t into ST0 ----
    if (t < nTiles) {
        long long p = t * TILE_M + grow;
        if (p >= P) p = 0;
        long long gi = is64 ? ((const long long*)g_isrc)[p]
                            : (long long)((const int*)g_isrc)[p];
        const char* src = (const char*)(g_src + gi * DHALF);
        uint32_t rswz = ((uint32_t)grow & 7) << 4;
#pragma unroll
        for (int i = 0; i < 16; i++) {
            uint32_t doff = (uint32_t)(grow * 512) +
                            (((uint32_t)(ghalf * 256 + i * 16)) ^ rswz);
            cp16(sb + SM_ST0 + doff, src + i * 16);
        }
        cp_commit();
    }

    for (; t < nTiles; t += grid, par ^= 1) {
        const long long base = t * TILE_M;
        const long long tnext = t + grid;
        const int hasNext = tnext < nTiles;

        // prefetch next-tile index early (hidden behind wait+convert)
        long long gi_next = 0;
        if (hasNext) {
            long long p = tnext * TILE_M + grow;
            if (p >= P) p = 0;
            gi_next = is64 ? ((const long long*)g_isrc)[p]
                           : (long long)((const int*)g_isrc)[p];
        }

        cp_wait0();
        __syncthreads();

        // ---- convert staging fp32 -> Ah/Al fp16 tiles ----
        {
            const uint32_t stg = par ? SM_ST1 : SM_ST0;
            const uint32_t rswz = ((uint32_t)crow & 7) << 4;
            const int lane8 = lid & 8;
#pragma unroll
            for (int i = 0; i < 16; i++) {
                int jj = i ^ lane8;   // phase-decorrelated column
                uint32_t soff = (uint32_t)(crow * 512) +
                                (((uint32_t)(chalf * 256 + jj * 16)) ^ rswz);
                float4 v = *(const float4*)(smem + stg + soff);
                __half2 h01 = __floats2half2_rn(v.x, v.y);
                __half2 h23 = __floats2half2_rn(v.z, v.w);
                float2 f01 = __half22float2(h01);
                float2 f23 = __half22float2(h23);
                __half2 l01 = __floats2half2_rn(v.x - f01.x, v.y - f01.y);
                __half2 l23 = __floats2half2_rn(v.z - f23.x, v.w - f23.y);
                uint32_t aoff = (uint32_t)(crow * ROWB) +
                                (uint32_t)(chalf * 64 + jj * 4) * 2;
                uint2 wh, wl;
                wh.x = *(uint32_t*)&h01; wh.y = *(uint32_t*)&h23;
                wl.x = *(uint32_t*)&l01; wl.y = *(uint32_t*)&l23;
                *(uint2*)(smem + SM_AH + aoff) = wh;
                *(uint2*)(smem + SM_AL + aoff) = wl;
            }
        }
        __syncthreads();   // A tiles ready; stage[par] free

        // ---- issue gather for next tile into other staging buffer ----
        if (hasNext) {
            const uint32_t stg = par ? SM_ST0 : SM_ST1;
            const char* src = (const char*)(g_src + gi_next * DHALF);
            uint32_t rswz = ((uint32_t)grow & 7) << 4;
#pragma unroll
            for (int i = 0; i < 16; i++) {
                uint32_t doff = (uint32_t)(grow * 512) +
                                (((uint32_t)(ghalf * 256 + i * 16)) ^ rswz);
                cp16(sb + stg + doff, src + i * 16);
            }
            cp_commit();
        }

        // ---- GEMM: c = (Ah + Al) * Bh, fp32 accum ----
        float c[4][4][4];
#pragma unroll
        for (int mt = 0; mt < 4; mt++)
#pragma unroll
            for (int nf = 0; nf < 4; nf++)
#pragma unroll
                for (int j = 0; j < 4; j++) c[mt][nf][j] = 0.0f;

#pragma unroll
        for (int ks = 0; ks < 8; ks++) {
            uint32_t ah[4][4], al[4][4];
#pragma unroll
            for (int mt = 0; mt < 4; mt++) {
                uint32_t ao = (uint32_t)((m0 + mt * 16 + a_row) * ROWB) +
                              (uint32_t)(ks * 16 + a_kad) * 2;
                ldsm_x4(ah[mt], sb + SM_AH + ao);
                ldsm_x4(al[mt], sb + SM_AL + ao);
            }
#pragma unroll
            for (int mt = 0; mt < 4; mt++)
#pragma unroll
                for (int nf = 0; nf < 4; nf++) {
                    mma16816(c[mt][nf], ah[mt], breg[ks][nf * 2], breg[ks][nf * 2 + 1]);
                    mma16816(c[mt][nf], al[mt], breg[ks][nf * 2], breg[ks][nf * 2 + 1]);
                }
        }

        // ---- epilogue: bias + relu + dot(W2) partials ----
        {
            const float* s_b1 = (const float*)(smem + SM_B1);
            const float* s_w2 = (const float*)(smem + SM_W2);
            const int tq = lid & 3;
            const int q = lid >> 2;
            float* part = (float*)(smem + SM_PART);
#pragma unroll
            for (int mt = 0; mt < 4; mt++) {
                float s0 = 0.0f, s1 = 0.0f;
#pragma unroll
                for (int nf = 0; nf < 4; nf++) {
                    int col = n0 + nf * 8 + tq * 2;
                    float ba = s_b1[col], bb = s_b1[col + 1];
                    float wa = s_w2[col], wb = s_w2[col + 1];
                    s0 = fmaf(fmaxf(c[mt][nf][0] + ba, 0.0f), wa, s0);
                    s0 = fmaf(fmaxf(c[mt][nf][1] + bb, 0.0f), wb, s0);
                    s1 = fmaf(fmaxf(c[mt][nf][2] + ba, 0.0f), wa, s1);
                    s1 = fmaf(fmaxf(c[mt][nf][3] + bb, 0.0f), wb, s1);
                }
                s0 += __shfl_xor_sync(0xFFFFFFFF, s0, 1);
                s0 += __shfl_xor_sync(0xFFFFFFFF, s0, 2);
                s1 += __shfl_xor_sync(0xFFFFFFFF, s1, 1);
                s1 += __shfl_xor_sync(0xFFFFFFFF, s1, 2);
                if (tq == 0) {
                    int row = m0 + mt * 16 + q;
                    part[wn * 128 + row] = s0;
                    part[wn * 128 + row + 8] = s1;
                }
            }
        }
        __syncthreads();

        if (tid < TILE_M) {
            long long p = base + tid;
            if (p < P) {
                const float* part = (const float*)(smem + SM_PART);
                out[p] = part[tid] + part[128 + tid] + part[256 + tid] +
                         part[384 + tid] + b2v;
            }
        }
        __syncthreads();   // partials + A tiles reusable next iteration
    }
}

// ---------------- launch ----------------
extern "C" void kernel_launch(void* const* d_in, const int* in_sizes, int n_in,
                              void* d_out, int out_size) {
    const float* g1 = (const float*)d_in[0];
    const float* g2 = (const float*)d_in[1];
    const void* il = d_in[2];
    const void* ir = d_in[3];
    const float* W1 = (const float*)d_in[4];
    const float* b1 = (const float*)d_in[5];
    const float* W2 = (const float*)d_in[6];
    const float* b2 = (const float*)d_in[7];
    long long P = (long long)in_sizes[2];
    long long Nn = (long long)in_sizes[0] / DHALF;

    pip_prep<<<(ED * ED + 255) / 256, 256>>>(W1, il, P, Nn);

    cudaFuncSetAttribute(pip_main, cudaFuncAttributeMaxDynamicSharedMemorySize, SMEM_BYTES);
    int nsm = 148;
    cudaDeviceGetAttribute(&nsm, cudaDevAttrMultiProcessorCount, 0);
    long long nTiles = (P + TILE_M - 1) / TILE_M;
    int grid = (nTiles < (long long)nsm) ? (int)nTiles : nsm;

    pip_main<<<grid, THREADS, SMEM_BYTES>>>(g1, g2, il, ir, b1, W2, b2,
                                            (float*)d_out, P, Nn);
}

// round 6
// speedup vs baseline: 1.3732x; 1.3732x over previous
#include <cuda_runtime.h>
#include <cuda_fp16.h>
#include <stdint.h>

#define ED 128
#define DHALF 64
#define TILE_M 128
#define THREADS 512
#define ROWB 272   // fp16 row stride in bytes (136 halfs) -> conflict-free ldmatrix

// ---------------- device globals ----------------
__device__ __half g_W1h[ED * ED];
__device__ int g_idx64;

// ---------------- helpers ----------------
__device__ __forceinline__ uint32_t smem_u32(const void* p) {
    uint32_t a;
    asm("{ .reg .u64 t; cvta.to.shared.u64 t, %1; cvt.u32.u64 %0, t; }" : "=r"(a) : "l"(p));
    return a;
}
__device__ __forceinline__ void ldsm_x4(uint32_t* r, uint32_t addr) {
    asm volatile("ldmatrix.sync.aligned.m8n8.x4.shared.b16 {%0,%1,%2,%3}, [%4];"
                 : "=r"(r[0]), "=r"(r[1]), "=r"(r[2]), "=r"(r[3]) : "r"(addr));
}
__device__ __forceinline__ void mma16816(float* c, const uint32_t* a, uint32_t b0, uint32_t b1) {
    asm volatile("mma.sync.aligned.m16n8k16.row.col.f32.f16.f16.f32 "
                 "{%0,%1,%2,%3}, {%4,%5,%6,%7}, {%8,%9}, {%0,%1,%2,%3};"
                 : "+f"(c[0]), "+f"(c[1]), "+f"(c[2]), "+f"(c[3])
                 : "r"(a[0]), "r"(a[1]), "r"(a[2]), "r"(a[3]), "r"(b0), "r"(b1));
}

// smem layout (bytes)
#define SM_PART 0                        // float[4][128]
#define SM_B1   2048                     // float[128]
#define SM_W2   2560                     // float[128]
#define SM_BH   3072                     // 128 rows x ROWB
#define SM_AH   (SM_BH + ED * ROWB)      // 128 rows x ROWB
#define SMEM_BYTES (SM_AH + TILE_M * ROWB)

// ---------------- prep: W1 -> fp16; sniff idx dtype ----------------
__global__ void pip_prep(const float* __restrict__ W1, const void* __restrict__ idxl,
                         long long P, long long Nnodes) {
    int i = blockIdx.x * blockDim.x + threadIdx.x;
    if (i < ED * ED) g_W1h[i] = __float2half_rn(W1[i]);
    if (blockIdx.x == 0 && threadIdx.x == 0) {
        const unsigned long long* p64 = (const unsigned long long*)idxl;
        long long n = 512;
        if (2 * n > P) n = P / 2;
        int ok = 1;
        for (long long k = 0; k < n; k++)
            if (p64[k] >= (unsigned long long)Nnodes) { ok = 0; break; }
        g_idx64 = ok;
    }
}

// ---------------- main persistent kernel ----------------
extern "C" __global__ void __launch_bounds__(THREADS, 1)
pip_main(const float* __restrict__ g1, const float* __restrict__ g2,
         const void* __restrict__ idxl, const void* __restrict__ idxr,
         const float* __restrict__ b1, const float* __restrict__ W2,
         const float* __restrict__ b2, float* __restrict__ out,
         long long P, long long Nnodes) {
    extern __shared__ char smem[];
    const uint32_t sb = smem_u32(smem);
    const int tid = threadIdx.x;
    const int wid = tid >> 5;
    const int lid = tid & 31;
    const int is64 = g_idx64;

    // ---- stage b1 / W2 / W1h(B tile, resident all kernel) ----
    for (int i = tid; i < ED; i += THREADS) {
        ((float*)(smem + SM_B1))[i] = b1[i];
        ((float*)(smem + SM_W2))[i] = W2[i];
    }
    for (int i = tid; i < ED * 32; i += THREADS) {  // uint2 = 4 halfs
        int n = i >> 5, kq = i & 31;
        *(uint2*)(smem + SM_BH + n * ROWB + kq * 8) = ((const uint2*)g_W1h)[i];
    }
    __syncthreads();

    // warp tiling: 4m x 4n, warp tile m32 x n32
    const int m0 = (wid >> 2) * 32;
    const int n0 = (wid & 3) * 32;
    const int a_row = (lid & 7) + ((lid >> 3) & 1) * 8;
    const int a_kad = ((lid >> 4) & 1) * 8;
    const int b_row = (lid & 7) + ((lid >> 4) & 1) * 8;
    const int b_kad = ((lid >> 3) & 1) * 8;

    // gather role: thread -> (row = tid>>2, sub = tid&3); sub 0,1 = left halves, 2,3 = right
    const int grow = tid >> 2;
    const int gsub = tid & 3;
    const void* isrc = (gsub < 2) ? idxl : idxr;
    const float* gsrc = (gsub < 2) ? g1 : g2;
    const int gqoff = (gsub & 1) * 8;  // float4 offset within the 64-float half

    const float b2v = b2[0];
    const long long nTiles = (P + TILE_M - 1) / TILE_M;
    const long long grid = gridDim.x;
    float* part = (float*)(smem + SM_PART);
    const float* s_b1 = (const float*)(smem + SM_B1);
    const float* s_w2 = (const float*)(smem + SM_W2);

    long long t = blockIdx.x;
    float4 v[8];
    long long gi_next = 0;

    // ---- prologue: idx(t) + data(t) + idx(t+grid) ----
    if (t < nTiles) {
        long long p = t * TILE_M + grow;
        if (p >= P) p = 0;
        long long gi = is64 ? ((const long long*)isrc)[p]
                            : (long long)((const int*)isrc)[p];
        const float4* src = (const float4*)(gsrc + gi * DHALF) + gqoff;
#pragma unroll
        for (int i = 0; i < 8; i++) v[i] = src[i];
        long long t2 = t + grid;
        if (t2 < nTiles) {
            long long p2 = t2 * TILE_M + grow;
            if (p2 >= P) p2 = 0;
            gi_next = is64 ? ((const long long*)isrc)[p2]
                           : (long long)((const int*)isrc)[p2];
        }
    }

    for (; t < nTiles; t += grid) {
        const long long base = t * TILE_M;

        // ---- STS: convert v (fp32) -> fp16 A tile ----
        {
            uint32_t abase = (uint32_t)(grow * ROWB + gsub * 64);
#pragma unroll
            for (int i = 0; i < 8; i++) {
                __half2 h01 = __floats2half2_rn(v[i].x, v[i].y);
                __half2 h23 = __floats2half2_rn(v[i].z, v[i].w);
                uint2 w;
                w.x = *(uint32_t*)&h01; w.y = *(uint32_t*)&h23;
                *(uint2*)(smem + SM_AH + abase + i * 8) = w;
            }
        }
        __syncthreads();  // A(t) ready

        // ---- issue next-tile gather (hidden under GEMM) ----
        const long long tn = t + grid;
        if (tn < nTiles) {
            const float4* src = (const float4*)(gsrc + gi_next * DHALF) + gqoff;
#pragma unroll
            for (int i = 0; i < 8; i++) v[i] = src[i];
            long long t2 = tn + grid;
            if (t2 < nTiles) {
                long long p2 = t2 * TILE_M + grow;
                if (p2 >= P) p2 = 0;
                gi_next = is64 ? ((const long long*)isrc)[p2]
                               : (long long)((const int*)isrc)[p2];
            }
        }

        // ---- GEMM: c = A * W1h^T ----
        float c[2][4][4];
#pragma unroll
        for (int mt = 0; mt < 2; mt++)
#pragma unroll
            for (int nf = 0; nf < 4; nf++)
#pragma unroll
                for (int j = 0; j < 4; j++) c[mt][nf][j] = 0.0f;

#pragma unroll
        for (int ks = 0; ks < 8; ks++) {
            uint32_t ah[2][4], bh[2][4];
#pragma unroll
            for (int mt = 0; mt < 2; mt++) {
                uint32_t ao = (uint32_t)((m0 + mt * 16 + a_row) * ROWB +
                                         (ks * 16 + a_kad) * 2);
                ldsm_x4(ah[mt], sb + SM_AH + ao);
            }
#pragma unroll
            for (int nq = 0; nq < 2; nq++) {
                uint32_t bo = (uint32_t)((n0 + nq * 16 + b_row) * ROWB +
                                         (ks * 16 + b_kad) * 2);
                ldsm_x4(bh[nq], sb + SM_BH + bo);
            }
#pragma unroll
            for (int mt = 0; mt < 2; mt++)
#pragma unroll
                for (int nq = 0; nq < 2; nq++)
#pragma unroll
                    for (int f = 0; f < 2; f++)
                        mma16816(c[mt][nq * 2 + f], ah[mt],
                                 bh[nq][2 * f], bh[nq][2 * f + 1]);
        }

        // ---- epilogue: bias + relu + dot(W2) partials ----
        {
            const int tq = lid & 3;
            const int q = lid >> 2;
            const int wn = wid & 3;
#pragma unroll
            for (int mt = 0; mt < 2; mt++) {
                float s0 = 0.0f, s1 = 0.0f;
#pragma unroll
                for (int nf = 0; nf < 4; nf++) {
                    int col = n0 + nf * 8 + tq * 2;
                    float ba = s_b1[col], bb = s_b1[col + 1];
                    float wa = s_w2[col], wb = s_w2[col + 1];
                    s0 = fmaf(fmaxf(c[mt][nf][0] + ba, 0.0f), wa, s0);
                    s0 = fmaf(fmaxf(c[mt][nf][1] + bb, 0.0f), wb, s0);
                    s1 = fmaf(fmaxf(c[mt][nf][2] + ba, 0.0f), wa, s1);
                    s1 = fmaf(fmaxf(c[mt][nf][3] + bb, 0.0f), wb, s1);
                }
                s0 += __shfl_xor_sync(0xFFFFFFFF, s0, 1);
                s0 += __shfl_xor_sync(0xFFFFFFFF, s0, 2);
                s1 += __shfl_xor_sync(0xFFFFFFFF, s1, 1);
                s1 += __shfl_xor_sync(0xFFFFFFFF, s1, 2);
                if (tq == 0) {
                    int row = m0 + mt * 16 + q;
                    part[wn * 128 + row] = s0;
                    part[wn * 128 + row + 8] = s1;
                }
            }
        }
        __syncthreads();  // partials ready; all A-reads done

        if (tid < TILE_M) {
            long long p = base + tid;
            if (p < P)
                out[p] = part[tid] + part[128 + tid] + part[256 + tid] +
                         part[384 + tid] + b2v;
        }
        // next iteration's A-tile STS is safe only after everyone read part[]
        // and the out-writers are done; the STS targets a different region than
        // part[], and the loop-top sync (A-ready) orders STS vs part reads.
    }
}

// ---------------- launch ----------------
extern "C" void kernel_launch(void* const* d_in, const int* in_sizes, int n_in,
                              void* d_out, int out_size) {
    const float* g1 = (const float*)d_in[0];
    const float* g2 = (const float*)d_in[1];
    const void* il = d_in[2];
    const void* ir = d_in[3];
    const float* W1 = (const float*)d_in[4];
    const float* b1 = (const float*)d_in[5];
    const float* W2 = (const float*)d_in[6];
    const float* b2 = (const float*)d_in[7];
    long long P = (long long)in_sizes[2];
    long long Nn = (long long)in_sizes[0] / DHALF;

    pip_prep<<<(ED * ED + 255) / 256, 256>>>(W1, il, P, Nn);

    cudaFuncSetAttribute(pip_main, cudaFuncAttributeMaxDynamicSharedMemorySize, SMEM_BYTES);
    int nsm = 148;
    cudaDeviceGetAttribute(&nsm, cudaDevAttrMultiProcessorCount, 0);
    long long nTiles = (P + TILE_M - 1) / TILE_M;
    int grid = (nTiles < (long long)nsm) ? (int)nTiles : nsm;

    pip_main<<<grid, THREADS, SMEM_BYTES>>>(g1, g2, il, ir, b1, W2, b2,
                                            (float*)d_out, P, Nn);
}

// round 7
// speedup vs baseline: 2.2037x; 1.6048x over previous
#include <cuda_runtime.h>
#include <cuda_fp16.h>
#include <stdint.h>

#define ED 128
#define DHALF 64
#define TILE_M 128
#define THREADS 512
#define ROWB 272   // fp16 row stride in bytes (136 halfs) -> conflict-free ldmatrix

// ---------------- device globals ----------------
__device__ __half g_W1h[ED * ED];
__device__ int g_idx64;

// ---------------- helpers ----------------
__device__ __forceinline__ uint32_t smem_u32(const void* p) {
    uint32_t a;
    asm("{ .reg .u64 t; cvta.to.shared.u64 t, %1; cvt.u32.u64 %0, t; }" : "=r"(a) : "l"(p));
    return a;
}
__device__ __forceinline__ void ldsm_x4(uint32_t* r, uint32_t addr) {
    asm volatile("ldmatrix.sync.aligned.m8n8.x4.shared.b16 {%0,%1,%2,%3}, [%4];"
                 : "=r"(r[0]), "=r"(r[1]), "=r"(r[2]), "=r"(r[3]) : "r"(addr));
}
__device__ __forceinline__ void mma16816(float* c, const uint32_t* a, uint32_t b0, uint32_t b1) {
    asm volatile("mma.sync.aligned.m16n8k16.row.col.f32.f16.f16.f32 "
                 "{%0,%1,%2,%3}, {%4,%5,%6,%7}, {%8,%9}, {%0,%1,%2,%3};"
                 : "+f"(c[0]), "+f"(c[1]), "+f"(c[2]), "+f"(c[3])
                 : "r"(a[0]), "r"(a[1]), "r"(a[2]), "r"(a[3]), "r"(b0), "r"(b1));
}

// smem layout (bytes)
#define SM_PART 0                        // float[4][128]
#define SM_B1   2048                     // float[128]
#define SM_W2   2560                     // float[128]
#define SM_BH   3072                     // 128 rows x ROWB
#define SM_AH   (SM_BH + ED * ROWB)      // 128 rows x ROWB
#define SMEM_BYTES (SM_AH + TILE_M * ROWB)

// ---------------- prep: W1 -> fp16; sniff idx dtype ----------------
__global__ void pip_prep(const float* __restrict__ W1, const void* __restrict__ idxl,
                         long long P, long long Nnodes) {
    int i = blockIdx.x * blockDim.x + threadIdx.x;
    if (i < ED * ED) g_W1h[i] = __float2half_rn(W1[i]);
    if (blockIdx.x == 0 && threadIdx.x == 0) {
        const unsigned long long* p64 = (const unsigned long long*)idxl;
        long long n = 512;
        if (2 * n > P) n = P / 2;
        int ok = 1;
        for (long long k = 0; k < n; k++)
            if (p64[k] >= (unsigned long long)Nnodes) { ok = 0; break; }
        g_idx64 = ok;
    }
}

// ---------------- main persistent kernel ----------------
extern "C" __global__ void __launch_bounds__(THREADS, 1)
pip_main(const float* __restrict__ g1, const float* __restrict__ g2,
         const void* __restrict__ idxl, const void* __restrict__ idxr,
         const float* __restrict__ b1, const float* __restrict__ W2,
         const float* __restrict__ b2, float* __restrict__ out,
         long long P, long long Nnodes) {
    extern __shared__ char smem[];
    const uint32_t sb = smem_u32(smem);
    const int tid = threadIdx.x;
    const int wid = tid >> 5;
    const int lid = tid & 31;
    const int is64 = g_idx64;

    // ---- stage b1 / W2 / W1h(B tile, resident all kernel) ----
    for (int i = tid; i < ED; i += THREADS) {
        ((float*)(smem + SM_B1))[i] = b1[i];
        ((float*)(smem + SM_W2))[i] = W2[i];
    }
    for (int i = tid; i < ED * 32; i += THREADS) {  // uint2 = 4 halfs
        int n = i >> 5, kq = i & 31;
        *(uint2*)(smem + SM_BH + n * ROWB + kq * 8) = ((const uint2*)g_W1h)[i];
    }
    __syncthreads();

    // warp tiling: 4m x 4n, warp tile m32 x n32
    const int m0 = (wid >> 2) * 32;
    const int n0 = (wid & 3) * 32;
    const int a_row = (lid & 7) + ((lid >> 3) & 1) * 8;
    const int a_kad = ((lid >> 4) & 1) * 8;
    const int b_row = (lid & 7) + ((lid >> 4) & 1) * 8;
    const int b_kad = ((lid >> 3) & 1) * 8;

    // gather role (coalesced): warp w owns tile rows [8w, 8w+8).
    // lanes 0-15 read left table, 16-31 right table; lane j = float4 j of the row.
    const int sslot = (lid >> 4) & 1;
    const int j = lid & 15;
    const void* isrc = sslot ? idxr : idxl;
    const float* gsrc = sslot ? g2 : g1;

    const float b2v = b2[0];
    const long long nTiles = (P + TILE_M - 1) / TILE_M;
    const long long grid = gridDim.x;
    float* part = (float*)(smem + SM_PART);
    const float* s_b1 = (const float*)(smem + SM_B1);
    const float* s_w2 = (const float*)(smem + SM_W2);

    long long t = blockIdx.x;
    float4 v[8];

    // ---- prologue: gather tile t ----
    if (t < nTiles) {
#pragma unroll
        for (int i = 0; i < 8; i++) {
            long long p = t * TILE_M + wid * 8 + i;
            if (p >= P) p = 0;
            long long gi = is64 ? ((const long long*)isrc)[p]
                                : (long long)((const int*)isrc)[p];
            v[i] = ((const float4*)(gsrc + gi * DHALF))[j];
        }
    }

    for (; t < nTiles; t += grid) {
        const long long base = t * TILE_M;

        // ---- STS: convert v (fp32) -> fp16 A tile ----
        // lane writes 8B at row (8w+i), byte col sslot*128 + j*8: two
        // contiguous 128B row segments per instr, conflict-free.
        {
            const uint32_t abase = (uint32_t)(wid * 8 * ROWB + sslot * 128 + j * 8);
#pragma unroll
            for (int i = 0; i < 8; i++) {
                __half2 h01 = __floats2half2_rn(v[i].x, v[i].y);
                __half2 h23 = __floats2half2_rn(v[i].z, v[i].w);
                uint2 w;
                w.x = *(uint32_t*)&h01; w.y = *(uint32_t*)&h23;
                *(uint2*)(smem + SM_AH + abase + i * ROWB) = w;
            }
        }
        __syncthreads();  // A(t) ready

        // ---- issue next-tile gather (hidden under GEMM) ----
        const long long tn = t + grid;
        if (tn < nTiles) {
#pragma unroll
            for (int i = 0; i < 8; i++) {
                long long p = tn * TILE_M + wid * 8 + i;
                if (p >= P) p = 0;
                long long gi = is64 ? ((const long long*)isrc)[p]
                                    : (long long)((const int*)isrc)[p];
                v[i] = ((const float4*)(gsrc + gi * DHALF))[j];
            }
        }

        // ---- GEMM: c = A * W1h^T ----
        float c[2][4][4];
#pragma unroll
        for (int mt = 0; mt < 2; mt++)
#pragma unroll
            for (int nf = 0; nf < 4; nf++)
#pragma unroll
                for (int jj = 0; jj < 4; jj++) c[mt][nf][jj] = 0.0f;

#pragma unroll
        for (int ks = 0; ks < 8; ks++) {
            uint32_t ah[2][4], bh[2][4];
#pragma unroll
            for (int mt = 0; mt < 2; mt++) {
                uint32_t ao = (uint32_t)((m0 + mt * 16 + a_row) * ROWB +
                                         (ks * 16 + a_kad) * 2);
                ldsm_x4(ah[mt], sb + SM_AH + ao);
            }
#pragma unroll
            for (int nq = 0; nq < 2; nq++) {
                uint32_t bo = (uint32_t)((n0 + nq * 16 + b_row) * ROWB +
                                         (ks * 16 + b_kad) * 2);
                ldsm_x4(bh[nq], sb + SM_BH + bo);
            }
#pragma unroll
            for (int mt = 0; mt < 2; mt++)
#pragma unroll
                for (int nq = 0; nq < 2; nq++)
#pragma unroll
                    for (int f = 0; f < 2; f++)
                        mma16816(c[mt][nq * 2 + f], ah[mt],
                                 bh[nq][2 * f], bh[nq][2 * f + 1]);
        }

        // ---- epilogue: bias + relu + dot(W2) partials ----
        {
            const int tq = lid & 3;
            const int q = lid >> 2;
            const int wn = wid & 3;
#pragma unroll
            for (int mt = 0; mt < 2; mt++) {
                float s0 = 0.0f, s1 = 0.0f;
#pragma unroll
                for (int nf = 0; nf < 4; nf++) {
                    int col = n0 + nf * 8 + tq * 2;
                    float ba = s_b1[col], bb = s_b1[col + 1];
                    float wa = s_w2[col], wb = s_w2[col + 1];
                    s0 = fmaf(fmaxf(c[mt][nf][0] + ba, 0.0f), wa, s0);
                    s0 = fmaf(fmaxf(c[mt][nf][1] + bb, 0.0f), wb, s0);
                    s1 = fmaf(fmaxf(c[mt][nf][2] + ba, 0.0f), wa, s1);
                    s1 = fmaf(fmaxf(c[mt][nf][3] + bb, 0.0f), wb, s1);
                }
                s0 += __shfl_xor_sync(0xFFFFFFFF, s0, 1);
                s0 += __shfl_xor_sync(0xFFFFFFFF, s0, 2);
                s1 += __shfl_xor_sync(0xFFFFFFFF, s1, 1);
                s1 += __shfl_xor_sync(0xFFFFFFFF, s1, 2);
                if (tq == 0) {
                    int row = m0 + mt * 16 + q;
                    part[wn * 128 + row] = s0;
                    part[wn * 128 + row + 8] = s1;
                }
            }
        }
        __syncthreads();  // partials ready; all A(t) reads done

        if (tid < TILE_M) {
            long long p = base + tid;
            if (p < P)
                out[p] = part[tid] + part[128 + tid] + part[256 + tid] +
                         part[384 + tid] + b2v;
        }
        // next iteration's STS targets SM_AH (disjoint from part[]); the
        // loop-top sync orders STS(t+1) vs this iteration's part[] reads.
    }
}

// ---------------- launch ----------------
extern "C" void kernel_launch(void* const* d_in, const int* in_sizes, int n_in,
                              void* d_out, int out_size) {
    const float* g1 = (const float*)d_in[0];
    const float* g2 = (const float*)d_in[1];
    const void* il = d_in[2];
    const void* ir = d_in[3];
    const float* W1 = (const float*)d_in[4];
    const float* b1 = (const float*)d_in[5];
    const float* W2 = (const float*)d_in[6];
    const float* b2 = (const float*)d_in[7];
    long long P = (long long)in_sizes[2];
    long long Nn = (long long)in_sizes[0] / DHALF;

    pip_prep<<<(ED * ED + 255) / 256, 256>>>(W1, il, P, Nn);

    cudaFuncSetAttribute(pip_main, cudaFuncAttributeMaxDynamicSharedMemorySize, SMEM_BYTES);
    int nsm = 148;
    cudaDeviceGetAttribute(&nsm, cudaDevAttrMultiProcessorCount, 0);
    long long nTiles = (P + TILE_M - 1) / TILE_M;
    int grid = (nTiles < (long long)nsm) ? (int)nTiles : nsm;

    pip_main<<<grid, THREADS, SMEM_BYTES>>>(g1, g2, il, ir, b1, W2, b2,
                                            (float*)d_out, P, Nn);
}